// round 4
// baseline (speedup 1.0000x reference)
#include <cuda_runtime.h>

#define NN    100000
#define NE    3200000
#define ETOT  (NE + NN)

// ---------------- scratch (device globals; allocation-free) ----------------
__device__ __align__(16) float g_h[NN * 32];      // per-node transformed features (current layer)
__device__ __align__(16) float g_agg[NN * 32];    // weighted-sum accumulator, layers 1-2 (stride 32)
__device__ __align__(16) float g_agg2[NN * 16];   // accumulator for layer 3 (stride 16)
__device__ __align__(8)  float g_asrc[NN * 2];    // alpha_src per node per head
__device__ __align__(8)  float g_adst[NN * 2];    // alpha_dst per node per head
__device__ __align__(8)  float g_sum[NN * 2];     // sum of exp weights per dst per head
__device__ int g_src[ETOT];
__device__ int g_dst[ETOT];
__device__ int g_is64;                            // 1 if edge_index is int64, 0 if int32

// ---------------- vector reductions (fire-and-forget L2 atomics) -----------
__device__ __forceinline__ void red_add4(float* p, float a, float b, float c, float d) {
    asm volatile("red.global.add.v4.f32 [%0], {%1,%2,%3,%4};"
                 :: "l"(p), "f"(a), "f"(b), "f"(c), "f"(d) : "memory");
}
__device__ __forceinline__ void red_add2(float* p, float a, float b) {
    asm volatile("red.global.add.v2.f32 [%0], {%1,%2};"
                 :: "l"(p), "f"(a), "f"(b) : "memory");
}
__device__ __forceinline__ void red_add1(float* p, float a) {
    asm volatile("red.global.add.f32 [%0], %1;"
                 :: "l"(p), "f"(a) : "memory");
}

// ---------------- dtype probe: int64 arrays have zero odd 32-bit words ------
__global__ void probe_dtype(const int* __restrict__ ei32) {
    __shared__ int nz;
    if (threadIdx.x == 0) nz = 0;
    __syncthreads();
    // sample first 256 odd words; for int64 data these are high-words == 0
    int v = ei32[2 * threadIdx.x + 1];
    if (v != 0) atomicOr(&nz, 1);
    __syncthreads();
    if (threadIdx.x == 0) g_is64 = (nz == 0) ? 1 : 0;
}

// ---------------- edge index conversion -> int32, append self-loops ---------
__global__ __launch_bounds__(256) void convert_edges(const void* __restrict__ ei,
                                                     int E, int n) {
    int i = blockIdx.x * 256 + threadIdx.x;
    int is64 = g_is64;
    if (i < E) {
        if (is64) {
            const long long* p = (const long long*)ei;
            g_src[i] = (int)p[i];
            g_dst[i] = (int)p[E + i];
        } else {
            const int* p = (const int*)ei;
            g_src[i] = p[i];
            g_dst[i] = p[E + i];
        }
    } else if (i < E + n) {
        int v = i - E;
        g_src[i] = v;
        g_dst[i] = v;
    }
}

// ---------------- layer-1 node pass (IN=3, OUT=32, H=2, C=16) ---------------
__global__ __launch_bounds__(256) void node_pass1(const float* __restrict__ x,
                                                  const float* __restrict__ W,
                                                  const float* __restrict__ aw,
                                                  const float* __restrict__ dw,
                                                  int n) {
    __shared__ float sW[3 * 32];
    __shared__ float sA[32], sB[32];
    int t = threadIdx.x;
    if (t < 96) sW[t] = W[t];
    if (t < 32) { sA[t] = aw[t]; sB[t] = dw[t]; }
    __syncthreads();
    int i = blockIdx.x * 256 + t;
    if (i >= n) return;

    float x0 = x[3 * i], x1 = x[3 * i + 1], x2 = x[3 * i + 2];
    float h[32];
#pragma unroll
    for (int o = 0; o < 32; o++)
        h[o] = x0 * sW[o] + x1 * sW[32 + o] + x2 * sW[64 + o];

    float4* hp = (float4*)(g_h + (size_t)i * 32);
#pragma unroll
    for (int k = 0; k < 8; k++)
        hp[k] = make_float4(h[4 * k], h[4 * k + 1], h[4 * k + 2], h[4 * k + 3]);

    float a0 = 0.f, a1 = 0.f, d0 = 0.f, d1 = 0.f;
#pragma unroll
    for (int c = 0; c < 16; c++) {
        a0 += h[c] * sA[c];           d0 += h[c] * sB[c];
        a1 += h[16 + c] * sA[16 + c]; d1 += h[16 + c] * sB[16 + c];
    }
    g_asrc[2 * i] = a0; g_asrc[2 * i + 1] = a1;
    g_adst[2 * i] = d0; g_adst[2 * i + 1] = d1;
    g_sum[2 * i] = 0.f; g_sum[2 * i + 1] = 0.f;

    float4 z = make_float4(0.f, 0.f, 0.f, 0.f);
    float4* zq = (float4*)(g_agg + (size_t)i * 32);
#pragma unroll
    for (int k = 0; k < 8; k++) zq[k] = z;
}

// ---------------- node pass layers 2/3: divide + bias + elu + GEMM ----------
// Previous layer always has 2 heads (IN=32 split 16/16).
template <int IN, int OUT, int H, bool TO2>
__global__ __launch_bounds__(256) void node_passN(const float* __restrict__ W,
                                                  const float* __restrict__ aw,
                                                  const float* __restrict__ dw,
                                                  const float* __restrict__ bias_prev,
                                                  int n) {
    __shared__ float sW[IN * OUT];
    __shared__ float sA[OUT], sB[OUT], sBias[IN];
    for (int j = threadIdx.x; j < IN * OUT; j += 256) sW[j] = W[j];
    if (threadIdx.x < OUT) { sA[threadIdx.x] = aw[threadIdx.x]; sB[threadIdx.x] = dw[threadIdx.x]; }
    if (threadIdx.x < IN)  sBias[threadIdx.x] = bias_prev[threadIdx.x];
    __syncthreads();
    int i = blockIdx.x * 256 + threadIdx.x;
    if (i >= n) return;

    float inv0 = 1.f / (g_sum[2 * i] + 1e-16f);
    float inv1 = 1.f / (g_sum[2 * i + 1] + 1e-16f);

    float feat[IN];
#pragma unroll
    for (int c = 0; c < IN; c++) {
        float v = g_agg[(size_t)i * IN + c] * ((c < IN / 2) ? inv0 : inv1) + sBias[c];
        feat[c] = (v > 0.f) ? v : expm1f(v);   // elu
    }

    float h[OUT];
#pragma unroll
    for (int o = 0; o < OUT; o++) h[o] = 0.f;
#pragma unroll
    for (int c = 0; c < IN; c++) {
        float f = feat[c];
#pragma unroll
        for (int o = 0; o < OUT; o++) h[o] += f * sW[c * OUT + o];
    }

    float4* hp = (float4*)(g_h + (size_t)i * OUT);
#pragma unroll
    for (int k = 0; k < OUT / 4; k++)
        hp[k] = make_float4(h[4 * k], h[4 * k + 1], h[4 * k + 2], h[4 * k + 3]);

    if (H == 2) {
        float a0 = 0.f, a1 = 0.f, d0 = 0.f, d1 = 0.f;
#pragma unroll
        for (int c = 0; c < 16; c++) {
            a0 += h[c] * sA[c];            d0 += h[c] * sB[c];
            a1 += h[16 + c] * sA[16 + c];  d1 += h[16 + c] * sB[16 + c];
        }
        g_asrc[2 * i] = a0; g_asrc[2 * i + 1] = a1;
        g_adst[2 * i] = d0; g_adst[2 * i + 1] = d1;
    } else {
        float a0 = 0.f, d0 = 0.f;
#pragma unroll
        for (int c = 0; c < 16; c++) { a0 += h[c] * sA[c]; d0 += h[c] * sB[c]; }
        g_asrc[2 * i] = a0; g_asrc[2 * i + 1] = 0.f;
        g_adst[2 * i] = d0; g_adst[2 * i + 1] = 0.f;
    }
    g_sum[2 * i] = 0.f; g_sum[2 * i + 1] = 0.f;

    float* zp = TO2 ? g_agg2 : g_agg;
    float4 z = make_float4(0.f, 0.f, 0.f, 0.f);
    float4* zq = (float4*)(zp + (size_t)i * OUT);
#pragma unroll
    for (int k = 0; k < OUT / 4; k++) zq[k] = z;
}

// ---------------- fused edge pass: w = exp(leaky(e)); agg += h*w; sum += w --
template <int OUT, int H, bool TO2>
__global__ __launch_bounds__(256) void edge_pass(int etot) {
    int e = blockIdx.x * 256 + threadIdx.x;
    if (e >= etot) return;
    int s = g_src[e], d = g_dst[e];

    float2 as = *(const float2*)(g_asrc + 2 * s);
    float2 ad = *(const float2*)(g_adst + 2 * d);

    float e0 = as.x + ad.x;
    e0 = fmaxf(e0, 0.2f * e0);                 // leaky_relu(·, 0.2)
    float w0 = __expf(e0);
    float w1 = 0.f;
    if (H == 2) {
        float e1 = as.y + ad.y;
        e1 = fmaxf(e1, 0.2f * e1);
        w1 = __expf(e1);
    }

    const float4* hp = (const float4*)(g_h + (size_t)s * OUT);
    float* op = (TO2 ? g_agg2 : g_agg) + (size_t)d * OUT;
#pragma unroll
    for (int k = 0; k < OUT / 4; k++) {
        float4 v = hp[k];
        float w = (H == 2 && k >= OUT / 8) ? w1 : w0;
        red_add4(op + 4 * k, v.x * w, v.y * w, v.z * w, v.w * w);
    }
    if (H == 2) red_add2(g_sum + 2 * d, w0, w1);
    else        red_add1(g_sum + 2 * d, w0);
}

// ---------------- finalize: divide + bias + elu -> embeddings; sigmoid head -
__global__ __launch_bounds__(256) void finalize(const float* __restrict__ b3,
                                                const float* __restrict__ Wout,
                                                const float* __restrict__ bout,
                                                float* __restrict__ out, int n) {
    __shared__ float sb[16], sw[16];
    if (threadIdx.x < 16) { sb[threadIdx.x] = b3[threadIdx.x]; sw[threadIdx.x] = Wout[threadIdx.x]; }
    __syncthreads();
    int i = blockIdx.x * 256 + threadIdx.x;
    if (i >= n) return;

    float inv = 1.f / (g_sum[2 * i] + 1e-16f);
    float acc = 0.f;
    float* eo = out + n + (size_t)i * 16;
#pragma unroll
    for (int c = 0; c < 16; c++) {
        float v = g_agg2[(size_t)i * 16 + c] * inv + sb[c];
        v = (v > 0.f) ? v : expm1f(v);         // elu -> embedding
        eo[c] = v;
        acc += v * sw[c];
    }
    out[i] = 1.f / (1.f + __expf(-(acc + bout[0])));
}

// ---------------- launch -----------------------------------------------------
extern "C" void kernel_launch(void* const* d_in, const int* in_sizes, int n_in,
                              void* d_out, int out_size) {
    const float* x  = (const float*)d_in[0];
    const void*  ei = d_in[1];                 // int32 OR int64 — probed on device
    const float *W1 = (const float*)d_in[2],  *as1 = (const float*)d_in[3],
                *ad1 = (const float*)d_in[4], *b1  = (const float*)d_in[5];
    const float *W2 = (const float*)d_in[6],  *as2 = (const float*)d_in[7],
                *ad2 = (const float*)d_in[8], *b2  = (const float*)d_in[9];
    const float *W3 = (const float*)d_in[10], *as3 = (const float*)d_in[11],
                *ad3 = (const float*)d_in[12], *b3 = (const float*)d_in[13];
    const float *Wout = (const float*)d_in[14], *bout = (const float*)d_in[15];

    int n    = in_sizes[0] / 3;
    int E    = in_sizes[1] / 2;
    int etot = E + n;
    int nb = (n + 255) / 256;
    int eb = (etot + 255) / 256;

    probe_dtype<<<1, 256>>>((const int*)ei);
    convert_edges<<<eb, 256>>>(ei, E, n);

    // layer 1
    node_pass1<<<nb, 256>>>(x, W1, as1, ad1, n);
    edge_pass<32, 2, false><<<eb, 256>>>(etot);

    // layer 2 (consumes layer-1 agg: divide + b1 + elu fused)
    node_passN<32, 32, 2, false><<<nb, 256>>>(W2, as2, ad2, b1, n);
    edge_pass<32, 2, false><<<eb, 256>>>(etot);

    // layer 3 (consumes layer-2 agg: divide + b2 + elu fused)
    node_passN<32, 16, 1, true><<<nb, 256>>>(W3, as3, ad3, b2, n);
    edge_pass<16, 1, true><<<eb, 256>>>(etot);

    // output head: elu(agg/s + b3) -> embeddings + sigmoid(linear)
    finalize<<<nb, 256>>>(b3, Wout, bout, (float*)d_out, n);
}

// round 5
// speedup vs baseline: 2.5677x; 2.5677x over previous
#include <cuda_runtime.h>

#define NN    100000
#define NE    3200000
#define ETOT  (NE + NN)
#define SCAN_B 512
#define NBLK   ((NN + SCAN_B - 1) / SCAN_B)   // 196

// ---------------- scratch (device globals; allocation-free) ----------------
__device__ __align__(16) float g_h[NN * 32];      // per-node transformed features
__device__ __align__(16) float g_agg[NN * 32];    // aggregated output, layers 1-2
__device__ __align__(16) float g_agg2[NN * 16];   // aggregated output, layer 3
__device__ __align__(8)  float g_asrc[NN * 2];    // alpha_src per node per head
__device__ __align__(8)  float g_adst[NN * 2];    // alpha_dst per node per head
__device__ __align__(8)  float g_sum[NN * 2];     // softmax denominator per dst per head
__device__ int g_src[ETOT];
__device__ int g_dst[ETOT];
__device__ int g_csr_src[ETOT];                   // src ids grouped by dst
__device__ int g_cnt[NN];
__device__ int g_off[NN + 1];
__device__ int g_cur[NN];
__device__ int g_bsum[NBLK];
__device__ int g_boff[NBLK];
__device__ int g_is64;

// ---------------- dtype probe: int64 arrays have zero odd 32-bit words ------
__global__ void probe_dtype(const int* __restrict__ ei32) {
    __shared__ int nz;
    if (threadIdx.x == 0) nz = 0;
    __syncthreads();
    int v = ei32[2 * threadIdx.x + 1];
    if (v != 0) atomicOr(&nz, 1);
    __syncthreads();
    if (threadIdx.x == 0) g_is64 = (nz == 0) ? 1 : 0;
}

__global__ __launch_bounds__(256) void zero_cnt(int n) {
    int i = blockIdx.x * 256 + threadIdx.x;
    if (i < n) g_cnt[i] = 0;
}

// ---------------- convert (either dtype) + self-loops + dst histogram -------
__global__ __launch_bounds__(256) void convert_hist(const void* __restrict__ ei,
                                                    int E, int n) {
    int i = blockIdx.x * 256 + threadIdx.x;
    int is64 = g_is64;
    int s, d;
    if (i < E) {
        if (is64) {
            const long long* p = (const long long*)ei;
            s = (int)p[i]; d = (int)p[E + i];
        } else {
            const int* p = (const int*)ei;
            s = p[i]; d = p[E + i];
        }
    } else if (i < E + n) {
        s = d = i - E;
    } else return;
    g_src[i] = s;
    g_dst[i] = d;
    atomicAdd(&g_cnt[d], 1);
}

// ---------------- 3-kernel exclusive scan of g_cnt -> g_off -----------------
__global__ __launch_bounds__(SCAN_B) void scan1(int n) {
    __shared__ int sm[SCAN_B];
    int t = threadIdx.x, i = blockIdx.x * SCAN_B + t;
    int v = (i < n) ? g_cnt[i] : 0;
    sm[t] = v; __syncthreads();
#pragma unroll
    for (int o = 1; o < SCAN_B; o <<= 1) {
        int x = (t >= o) ? sm[t - o] : 0;
        __syncthreads();
        sm[t] += x;
        __syncthreads();
    }
    if (i < n) g_off[i] = sm[t] - v;
    if (t == SCAN_B - 1) g_bsum[blockIdx.x] = sm[t];
}

__global__ void scan2(int nb) {
    __shared__ int sm[256];
    int t = threadIdx.x;
    int v = (t < nb) ? g_bsum[t] : 0;
    sm[t] = v; __syncthreads();
#pragma unroll
    for (int o = 1; o < 256; o <<= 1) {
        int x = (t >= o) ? sm[t - o] : 0;
        __syncthreads();
        sm[t] += x;
        __syncthreads();
    }
    if (t < nb) g_boff[t] = sm[t] - v;
}

__global__ __launch_bounds__(256) void scan3(int n, int etot) {
    int i = blockIdx.x * 256 + threadIdx.x;
    if (i < n) {
        int v = g_off[i] + g_boff[i / SCAN_B];
        g_off[i] = v;
        g_cur[i] = v;
    }
    if (i == 0) g_off[n] = etot;
}

__global__ __launch_bounds__(256) void scatter(int etot) {
    int i = blockIdx.x * 256 + threadIdx.x;
    if (i >= etot) return;
    int d = g_dst[i];
    int p = atomicAdd(&g_cur[d], 1);
    g_csr_src[p] = g_src[i];
}

// ---------------- layer-1 node pass (IN=3, OUT=32, H=2, C=16) ---------------
__global__ __launch_bounds__(256) void node_pass1(const float* __restrict__ x,
                                                  const float* __restrict__ W,
                                                  const float* __restrict__ aw,
                                                  const float* __restrict__ dw,
                                                  int n) {
    __shared__ float sW[3 * 32];
    __shared__ float sA[32], sB[32];
    int t = threadIdx.x;
    if (t < 96) sW[t] = W[t];
    if (t < 32) { sA[t] = aw[t]; sB[t] = dw[t]; }
    __syncthreads();
    int i = blockIdx.x * 256 + t;
    if (i >= n) return;

    float x0 = x[3 * i], x1 = x[3 * i + 1], x2 = x[3 * i + 2];
    float h[32];
#pragma unroll
    for (int o = 0; o < 32; o++)
        h[o] = x0 * sW[o] + x1 * sW[32 + o] + x2 * sW[64 + o];

    float4* hp = (float4*)(g_h + (size_t)i * 32);
#pragma unroll
    for (int k = 0; k < 8; k++)
        hp[k] = make_float4(h[4 * k], h[4 * k + 1], h[4 * k + 2], h[4 * k + 3]);

    float a0 = 0.f, a1 = 0.f, d0 = 0.f, d1 = 0.f;
#pragma unroll
    for (int c = 0; c < 16; c++) {
        a0 += h[c] * sA[c];           d0 += h[c] * sB[c];
        a1 += h[16 + c] * sA[16 + c]; d1 += h[16 + c] * sB[16 + c];
    }
    g_asrc[2 * i] = a0; g_asrc[2 * i + 1] = a1;
    g_adst[2 * i] = d0; g_adst[2 * i + 1] = d1;
}

// ---------------- node pass layers 2/3: divide + bias + elu + GEMM ----------
template <int IN, int OUT, int H>
__global__ __launch_bounds__(256) void node_passN(const float* __restrict__ W,
                                                  const float* __restrict__ aw,
                                                  const float* __restrict__ dw,
                                                  const float* __restrict__ bias_prev,
                                                  int n) {
    __shared__ float sW[IN * OUT];
    __shared__ float sA[OUT], sB[OUT], sBias[IN];
    for (int j = threadIdx.x; j < IN * OUT; j += 256) sW[j] = W[j];
    if (threadIdx.x < OUT) { sA[threadIdx.x] = aw[threadIdx.x]; sB[threadIdx.x] = dw[threadIdx.x]; }
    if (threadIdx.x < IN)  sBias[threadIdx.x] = bias_prev[threadIdx.x];
    __syncthreads();
    int i = blockIdx.x * 256 + threadIdx.x;
    if (i >= n) return;

    float inv0 = 1.f / (g_sum[2 * i] + 1e-16f);
    float inv1 = 1.f / (g_sum[2 * i + 1] + 1e-16f);

    float feat[IN];
#pragma unroll
    for (int c = 0; c < IN; c++) {
        float v = g_agg[(size_t)i * IN + c] * ((c < IN / 2) ? inv0 : inv1) + sBias[c];
        feat[c] = (v > 0.f) ? v : expm1f(v);   // elu
    }

    float h[OUT];
#pragma unroll
    for (int o = 0; o < OUT; o++) h[o] = 0.f;
#pragma unroll
    for (int c = 0; c < IN; c++) {
        float f = feat[c];
#pragma unroll
        for (int o = 0; o < OUT; o++) h[o] += f * sW[c * OUT + o];
    }

    float4* hp = (float4*)(g_h + (size_t)i * OUT);
#pragma unroll
    for (int k = 0; k < OUT / 4; k++)
        hp[k] = make_float4(h[4 * k], h[4 * k + 1], h[4 * k + 2], h[4 * k + 3]);

    if (H == 2) {
        float a0 = 0.f, a1 = 0.f, d0 = 0.f, d1 = 0.f;
#pragma unroll
        for (int c = 0; c < 16; c++) {
            a0 += h[c] * sA[c];            d0 += h[c] * sB[c];
            a1 += h[16 + c] * sA[16 + c];  d1 += h[16 + c] * sB[16 + c];
        }
        g_asrc[2 * i] = a0; g_asrc[2 * i + 1] = a1;
        g_adst[2 * i] = d0; g_adst[2 * i + 1] = d1;
    } else {
        float a0 = 0.f, d0 = 0.f;
#pragma unroll
        for (int c = 0; c < 16; c++) { a0 += h[c] * sA[c]; d0 += h[c] * sB[c]; }
        g_asrc[2 * i] = a0; g_asrc[2 * i + 1] = 0.f;
        g_adst[2 * i] = d0; g_adst[2 * i + 1] = 0.f;
    }
}

// ---------------- CSR edge pass: warp per dst, OUT/4 lanes per edge ---------
// Accumulates sum(h[src]*w) and sum(w) entirely in registers; one coalesced
// store per node. No atomics.
template <int OUT, int H, bool TO2>
__global__ __launch_bounds__(256) void edge_csr(int n) {
    constexpr int LPE = OUT / 4;   // lanes per edge (8 or 4)
    constexpr int EPW = 32 / LPE;  // edges in flight per warp (4 or 8)
    int warp = (blockIdx.x * 256 + threadIdx.x) >> 5;
    if (warp >= n) return;
    int d = warp;
    int lane = threadIdx.x & 31;
    int grp = lane / LPE;
    int l = lane % LPE;

    int start = g_off[d];
    int end   = g_off[d + 1];
    float2 ad = *(const float2*)(g_adst + 2 * d);

    float ax = 0.f, ay = 0.f, az = 0.f, aw_ = 0.f;
    float ws0 = 0.f, ws1 = 0.f;

    for (int e = start + grp; e < end; e += EPW) {
        int s = g_csr_src[e];
        float2 as = *(const float2*)(g_asrc + 2 * s);

        float e0 = as.x + ad.x;
        e0 = fmaxf(e0, 0.2f * e0);
        float w0 = __expf(e0);
        float w1 = 0.f;
        if (H == 2) {
            float e1 = as.y + ad.y;
            e1 = fmaxf(e1, 0.2f * e1);
            w1 = __expf(e1);
        }
        if (l == 0) { ws0 += w0; ws1 += w1; }

        float w = (H == 2 && l >= LPE / 2) ? w1 : w0;
        float4 v = ((const float4*)(g_h + (size_t)s * OUT))[l];
        ax += v.x * w; ay += v.y * w; az += v.z * w; aw_ += v.w * w;
    }

    // reduce across edge groups (lanes with equal l)
#pragma unroll
    for (int off = LPE; off < 32; off <<= 1) {
        ax  += __shfl_xor_sync(0xffffffffu, ax,  off);
        ay  += __shfl_xor_sync(0xffffffffu, ay,  off);
        az  += __shfl_xor_sync(0xffffffffu, az,  off);
        aw_ += __shfl_xor_sync(0xffffffffu, aw_, off);
        ws0 += __shfl_xor_sync(0xffffffffu, ws0, off);
        if (H == 2) ws1 += __shfl_xor_sync(0xffffffffu, ws1, off);
    }

    float* op = (TO2 ? g_agg2 : g_agg) + (size_t)d * OUT;
    if (lane < LPE)
        ((float4*)op)[lane] = make_float4(ax, ay, az, aw_);
    if (lane == 0) {
        g_sum[2 * d]     = ws0;
        g_sum[2 * d + 1] = (H == 2) ? ws1 : 0.f;
    }
}

// ---------------- finalize: divide + bias + elu -> embeddings; sigmoid head -
__global__ __launch_bounds__(256) void finalize(const float* __restrict__ b3,
                                                const float* __restrict__ Wout,
                                                const float* __restrict__ bout,
                                                float* __restrict__ out, int n) {
    __shared__ float sb[16], sw[16];
    if (threadIdx.x < 16) { sb[threadIdx.x] = b3[threadIdx.x]; sw[threadIdx.x] = Wout[threadIdx.x]; }
    __syncthreads();
    int i = blockIdx.x * 256 + threadIdx.x;
    if (i >= n) return;

    float inv = 1.f / (g_sum[2 * i] + 1e-16f);
    float acc = 0.f;
    float* eo = out + n + (size_t)i * 16;
#pragma unroll
    for (int c = 0; c < 16; c++) {
        float v = g_agg2[(size_t)i * 16 + c] * inv + sb[c];
        v = (v > 0.f) ? v : expm1f(v);         // elu -> embedding
        eo[c] = v;
        acc += v * sw[c];
    }
    out[i] = 1.f / (1.f + __expf(-(acc + bout[0])));
}

// ---------------- launch -----------------------------------------------------
extern "C" void kernel_launch(void* const* d_in, const int* in_sizes, int n_in,
                              void* d_out, int out_size) {
    const float* x  = (const float*)d_in[0];
    const void*  ei = d_in[1];
    const float *W1 = (const float*)d_in[2],  *as1 = (const float*)d_in[3],
                *ad1 = (const float*)d_in[4], *b1  = (const float*)d_in[5];
    const float *W2 = (const float*)d_in[6],  *as2 = (const float*)d_in[7],
                *ad2 = (const float*)d_in[8], *b2  = (const float*)d_in[9];
    const float *W3 = (const float*)d_in[10], *as3 = (const float*)d_in[11],
                *ad3 = (const float*)d_in[12], *b3 = (const float*)d_in[13];
    const float *Wout = (const float*)d_in[14], *bout = (const float*)d_in[15];

    int n    = in_sizes[0] / 3;
    int E    = in_sizes[1] / 2;
    int etot = E + n;
    int nb = (n + 255) / 256;
    int eb = (etot + 255) / 256;
    int wb = (n * 32 + 255) / 256;          // warp-per-node grids
    int sb = (n + SCAN_B - 1) / SCAN_B;

    // ---- CSR build (graph is layer-invariant; built once per launch) ----
    probe_dtype<<<1, 256>>>((const int*)ei);
    zero_cnt<<<nb, 256>>>(n);
    convert_hist<<<eb, 256>>>(ei, E, n);
    scan1<<<sb, SCAN_B>>>(n);
    scan2<<<1, 256>>>(sb);
    scan3<<<nb, 256>>>(n, etot);
    scatter<<<eb, 256>>>(etot);

    // ---- layer 1 ----
    node_pass1<<<nb, 256>>>(x, W1, as1, ad1, n);
    edge_csr<32, 2, false><<<wb, 256>>>(n);

    // ---- layer 2 ----
    node_passN<32, 32, 2><<<nb, 256>>>(W2, as2, ad2, b1, n);
    edge_csr<32, 2, false><<<wb, 256>>>(n);

    // ---- layer 3 ----
    node_passN<32, 16, 1><<<nb, 256>>>(W3, as3, ad3, b2, n);
    edge_csr<16, 1, true><<<wb, 256>>>(n);

    // ---- output head ----
    finalize<<<nb, 256>>>(b3, Wout, bout, (float*)d_out, n);
}